// round 1
// baseline (speedup 1.0000x reference)
#include <cuda_runtime.h>
#include <math.h>

#define Bn 8
#define Cn 64
#define On 64
#define Hn 128
#define Wn 128
#define HWn 16384
#define KKn 9

// scratch for sigmoid(mask conv): 8*9*128*128 floats = 4.7MB
__device__ float g_mask[Bn * KKn * HWn];

// ---------------------------------------------------------------------------
// Kernel A: fused 3x3 conv producing 18 offset channels (-> d_out offset
// region) and 9 mask channels (sigmoid -> g_mask). GEMM formulation:
// per block = one output row (128 px) of one batch; K = C*9 = 576, chunked 72.
// Thread tile: 4 px x 4 oc (oc padded 27 -> 32, slots 27..35 zero weights).
// ---------------------------------------------------------------------------
__global__ __launch_bounds__(256) void conv_offmask_kernel(
    const float* __restrict__ x,
    const float* __restrict__ p_w, const float* __restrict__ p_b,
    const float* __restrict__ m_w, const float* __restrict__ m_b,
    float* __restrict__ offs_out)
{
    __shared__ float sA[72 * 128];   // 36864 B
    __shared__ float sW[72 * 36];    // 10368 B
    const int h = blockIdx.x, b = blockIdx.y;
    const int tid = threadIdx.x;
    const int tx = tid & 31, ty = tid >> 5;   // ty 0..7 -> oc group ty*4
    const int row = h * Wn;

    float acc[4][4] = {};

    for (int c0 = 0; c0 < Cn; c0 += 8) {
        // stage A: im2col values for this 8-channel chunk
        #pragma unroll 4
        for (int j = 0; j < 36; ++j) {
            int e = tid + j * 256;            // 0..9215
            int kk = e >> 7, i = e & 127;     // kk: (c_local*9 + tap)
            int c = c0 + kk / 9;
            int t = kk - (kk / 9) * 9;
            int y  = h - 1 + t / 3;
            int xc = i - 1 + (t - (t / 3) * 3);
            float v = 0.f;
            if ((unsigned)y < Hn && (unsigned)xc < Wn)
                v = x[(((size_t)(b * Cn + c)) << 14) + y * Wn + xc];
            sA[kk * 128 + i] = v;
        }
        // stage W: 27 real output channels + padding
        for (int e = tid; e < 72 * 36; e += 256) {
            int kk = e % 72, o = e / 72;
            float v = 0.f;
            if (o < 18)      v = p_w[o * 576 + c0 * 9 + kk];
            else if (o < 27) v = m_w[(o - 18) * 576 + c0 * 9 + kk];
            sW[kk * 36 + o] = v;
        }
        __syncthreads();

        #pragma unroll 4
        for (int kk = 0; kk < 72; ++kk) {
            float a0 = sA[kk * 128 + tx];
            float a1 = sA[kk * 128 + tx + 32];
            float a2 = sA[kk * 128 + tx + 64];
            float a3 = sA[kk * 128 + tx + 96];
            float4 wv = *(const float4*)&sW[kk * 36 + ty * 4];
            acc[0][0] = fmaf(a0, wv.x, acc[0][0]);
            acc[0][1] = fmaf(a0, wv.y, acc[0][1]);
            acc[0][2] = fmaf(a0, wv.z, acc[0][2]);
            acc[0][3] = fmaf(a0, wv.w, acc[0][3]);
            acc[1][0] = fmaf(a1, wv.x, acc[1][0]);
            acc[1][1] = fmaf(a1, wv.y, acc[1][1]);
            acc[1][2] = fmaf(a1, wv.z, acc[1][2]);
            acc[1][3] = fmaf(a1, wv.w, acc[1][3]);
            acc[2][0] = fmaf(a2, wv.x, acc[2][0]);
            acc[2][1] = fmaf(a2, wv.y, acc[2][1]);
            acc[2][2] = fmaf(a2, wv.z, acc[2][2]);
            acc[2][3] = fmaf(a2, wv.w, acc[2][3]);
            acc[3][0] = fmaf(a3, wv.x, acc[3][0]);
            acc[3][1] = fmaf(a3, wv.y, acc[3][1]);
            acc[3][2] = fmaf(a3, wv.z, acc[3][2]);
            acc[3][3] = fmaf(a3, wv.w, acc[3][3]);
        }
        __syncthreads();
    }

    #pragma unroll
    for (int q = 0; q < 4; ++q) {
        int o = ty * 4 + q;
        if (o < 18) {
            float bias = p_b[o];
            #pragma unroll
            for (int r = 0; r < 4; ++r)
                offs_out[(((size_t)(b * 18 + o)) << 14) + row + tx + 32 * r] =
                    acc[r][q] + bias;
        } else if (o < 27) {
            float bias = m_b[o - 18];
            #pragma unroll
            for (int r = 0; r < 4; ++r) {
                float v = acc[r][q] + bias;
                g_mask[(((size_t)(b * 9 + (o - 18))) << 14) + row + tx + 32 * r] =
                    1.f / (1.f + expf(-v));
            }
        }
    }
}

// ---------------------------------------------------------------------------
// Kernel B: modulated deformable conv as tiled SGEMM.
// Block = one output row (128 px) x all 64 output channels of one batch.
// Per-(px,tap): 4 clamped corner indices + 4 bilinear weights with mask &
// validity folded in, computed once into smem. K = 576 in chunks of 72
// (8 input channels). Thread tile 4 px x 8 oc.
// ---------------------------------------------------------------------------
__global__ __launch_bounds__(256) void deform_kernel(
    const float* __restrict__ x,
    const float* __restrict__ offs,
    const float* __restrict__ d_w, const float* __restrict__ d_b,
    float* __restrict__ out)
{
    extern __shared__ float smem[];
    float* sA = smem;                         // 72*128  = 36864 B
    float* sW = sA + 72 * 128;                // 72*68   = 19584 B
    int4*   spos = (int4*)(sW + 72 * 68);     // 9*128*16 = 18432 B
    float4* swt  = (float4*)(spos + KKn * Wn);// 9*128*16 = 18432 B

    const int h = blockIdx.x, b = blockIdx.y;
    const int tid = threadIdx.x;
    const int tx = tid & 31, ty = tid >> 5;   // ty 0..7 -> oc group ty*8
    const int row = h * Wn;

    // precompute bilinear corner indices + (mask*validity)-folded weights
    for (int e = tid; e < KKn * Wn; e += 256) {
        int i = e & 127, k = e >> 7;
        float dy = offs[(((size_t)(b * 18 + 2 * k)) << 14) + row + i];
        float dx = offs[(((size_t)(b * 18 + 2 * k + 1)) << 14) + row + i];
        float m  = g_mask[(((size_t)(b * 9 + k)) << 14) + row + i];
        int ki = k / 3, kj = k - ki * 3;
        float py = (float)(h - 1 + ki) + dy;
        float px = (float)(i - 1 + kj) + dx;
        float y0f = floorf(py), x0f = floorf(px);
        float fy = py - y0f, fx = px - x0f;
        int y0 = (int)y0f, x0 = (int)x0f;
        int y1 = y0 + 1, x1 = x0 + 1;
        float vy0 = ((unsigned)y0 < Hn) ? 1.f : 0.f;
        float vy1 = ((unsigned)y1 < Hn) ? 1.f : 0.f;
        float vx0 = ((unsigned)x0 < Wn) ? 1.f : 0.f;
        float vx1 = ((unsigned)x1 < Wn) ? 1.f : 0.f;
        float gy = 1.f - fy, gx = 1.f - fx;
        float4 wq;
        wq.x = gy * gx * m * vy0 * vx0;
        wq.y = gy * fx * m * vy0 * vx1;
        wq.z = fy * gx * m * vy1 * vx0;
        wq.w = fy * fx * m * vy1 * vx1;
        int cy0 = min(max(y0, 0), Hn - 1) * Wn;
        int cy1 = min(max(y1, 0), Hn - 1) * Wn;
        int cx0 = min(max(x0, 0), Wn - 1);
        int cx1 = min(max(x1, 0), Wn - 1);
        spos[e] = make_int4(cy0 + cx0, cy0 + cx1, cy1 + cx0, cy1 + cx1);
        swt[e]  = wq;
    }
    __syncthreads();

    float acc[4][8] = {};

    for (int c0 = 0; c0 < Cn; c0 += 8) {
        // stage A: gathered+weighted samples. Warp lanes = consecutive pixels
        // of the same (channel, tap) -> coalesced-ish corner loads.
        #pragma unroll 4
        for (int j = 0; j < 36; ++j) {
            int e = tid + j * 256;            // 0..9215
            int kk = e >> 7, i = e & 127;
            int k = kk % 9;
            const float* plane =
                x + (((size_t)(b * Cn + c0 + kk / 9)) << 14);
            int4  p4 = spos[(k << 7) + i];
            float4 w4 = swt[(k << 7) + i];
            float v = w4.x * __ldg(plane + p4.x)
                    + w4.y * __ldg(plane + p4.y)
                    + w4.z * __ldg(plane + p4.z)
                    + w4.w * __ldg(plane + p4.w);
            sA[kk * 128 + i] = v;
        }
        // stage W: weights transposed to [kk][o], coalesced read of d_w
        #pragma unroll
        for (int j = 0; j < 18; ++j) {
            int e = tid + j * 256;            // 0..4607
            int kk = e % 72, o = e / 72;
            sW[kk * 68 + o] = d_w[o * 576 + c0 * 9 + kk];
        }
        __syncthreads();

        #pragma unroll 4
        for (int kk = 0; kk < 72; ++kk) {
            float a0 = sA[kk * 128 + tx];
            float a1 = sA[kk * 128 + tx + 32];
            float a2 = sA[kk * 128 + tx + 64];
            float a3 = sA[kk * 128 + tx + 96];
            float4 w0 = *(const float4*)&sW[kk * 68 + ty * 8];
            float4 w1 = *(const float4*)&sW[kk * 68 + ty * 8 + 4];
            float wr[8] = {w0.x, w0.y, w0.z, w0.w, w1.x, w1.y, w1.z, w1.w};
            float ar[4] = {a0, a1, a2, a3};
            #pragma unroll
            for (int r = 0; r < 4; ++r)
                #pragma unroll
                for (int q = 0; q < 8; ++q)
                    acc[r][q] = fmaf(ar[r], wr[q], acc[r][q]);
        }
        __syncthreads();
    }

    #pragma unroll
    for (int q = 0; q < 8; ++q) {
        int o = ty * 8 + q;
        float bias = __ldg(d_b + o);
        #pragma unroll
        for (int r = 0; r < 4; ++r)
            out[(((size_t)(b * On + o)) << 14) + row + tx + 32 * r] =
                acc[r][q] + bias;
    }
}

// ---------------------------------------------------------------------------

extern "C" void kernel_launch(void* const* d_in, const int* in_sizes, int n_in,
                              void* d_out, int out_size) {
    const float* x    = (const float*)d_in[0];
    const float* p_w  = (const float*)d_in[1];
    const float* p_b  = (const float*)d_in[2];
    const float* m_w  = (const float*)d_in[3];
    const float* m_b  = (const float*)d_in[4];
    const float* d_wp = (const float*)d_in[5];
    const float* d_bp = (const float*)d_in[6];

    float* out = (float*)d_out;                         // [8,64,128,128]
    float* offs_out = out + (size_t)Bn * On * HWn;      // [8,18,128,128]

    const int smemB = (72 * 128 + 72 * 68) * 4 + KKn * Wn * 16 * 2;  // 93312
    cudaFuncSetAttribute(deform_kernel,
                         cudaFuncAttributeMaxDynamicSharedMemorySize, smemB);

    dim3 grid(Hn, Bn);
    conv_offmask_kernel<<<grid, 256>>>(x, p_w, p_b, m_w, m_b, offs_out);
    deform_kernel<<<grid, 256, smemB>>>(x, offs_out, d_wp, d_bp, out);
}